// round 16
// baseline (speedup 1.0000x reference)
#include <cuda_runtime.h>
#include <cuda_fp16.h>
#include <cstdint>
#include <math.h>

// Problem constants
#define B_  4
#define T_  2048
#define C_  1024
#define H_  16
#define D_  64
#define M_  (B_*T_)   // 8192

// Scratch (allocation-free rule: __device__ globals)
__device__ __half g_Qh[M_ * C_];
__device__ __half g_Kh[M_ * C_];
__device__ __half g_Vh[M_ * C_];
__device__ __half g_xh[M_ * C_];
__device__ __half g_wh[4 * C_ * C_];
__device__ __half g_Oh[M_ * C_];
__device__ int    g_mflag[B_ * 16 * 32];
__device__ int    g_cnt_qkv[B_];      // GEMM completions per batch (target 384)
__device__ int    g_cnt_att[64];      // attention completions per (b,qt) (target 16)

// ---------------------------------------------------------------------------
// Common PTX helpers
// ---------------------------------------------------------------------------
__device__ __forceinline__ uint32_t smem_u32a(const void* p){
    uint32_t a;
    asm("{ .reg .u64 t; cvta.to.shared.u64 t, %1; cvt.u32.u64 %0, t; }" : "=r"(a) : "l"(p));
    return a;
}
__device__ __forceinline__ void mma16816(float* d, const uint32_t* a, const uint32_t* b){
    asm volatile("mma.sync.aligned.m16n8k16.row.col.f32.f16.f16.f32 "
        "{%0,%1,%2,%3}, {%4,%5,%6,%7}, {%8,%9}, {%0,%1,%2,%3};"
        : "+f"(d[0]), "+f"(d[1]), "+f"(d[2]), "+f"(d[3])
        : "r"(a[0]), "r"(a[1]), "r"(a[2]), "r"(a[3]), "r"(b[0]), "r"(b[1]));
}
__device__ __forceinline__ void ldsm4(uint32_t* r, uint32_t addr){
    asm volatile("ldmatrix.sync.aligned.m8n8.x4.shared.b16 {%0,%1,%2,%3}, [%4];"
        : "=r"(r[0]), "=r"(r[1]), "=r"(r[2]), "=r"(r[3]) : "r"(addr));
}
__device__ __forceinline__ void ldsm4t(uint32_t* r, uint32_t addr){
    asm volatile("ldmatrix.sync.aligned.m8n8.x4.trans.shared.b16 {%0,%1,%2,%3}, [%4];"
        : "=r"(r[0]), "=r"(r[1]), "=r"(r[2]), "=r"(r[3]) : "r"(addr));
}
__device__ __forceinline__ uint32_t packe(float a, float b){
    __half2 h = __floats2half2_rn(a, b);
    return *(uint32_t*)&h;
}
__device__ __forceinline__ float ex2f(float x){
    float y;
    asm("ex2.approx.f32 %0, %1;" : "=f"(y) : "f"(x));
    return y;
}
#define CP16(dst, src) asm volatile("cp.async.cg.shared.global [%0], [%1], 16;" :: "r"(dst), "l"(src))
#define CP_COMMIT()    asm volatile("cp.async.commit_group;")
#define CP_WAIT1()     asm volatile("cp.async.wait_group 1;")
#define CP_WAIT0()     asm volatile("cp.async.wait_group 0;")

// Producer/consumer sync (classic threadFenceReduction pattern)
__device__ __forceinline__ void bump_counter(int* c){
    __threadfence();
    __syncthreads();
    if (threadIdx.x == 0) atomicAdd(c, 1);
}
__device__ __forceinline__ void wait_counter(int* c, int target){
    if (threadIdx.x == 0) {
        while (*((volatile int*)c) < target) __nanosleep(128);
    }
    __syncthreads();
    __threadfence();
}

// ---------------------------------------------------------------------------
// Prep kernel: fp32->fp16 converts (x + 4 W), mask pre-scan, counter zeroing.
// grid = 12288 convert blocks + 2048 mask blocks, 256 threads.
// ---------------------------------------------------------------------------
#define XN_  (M_*C_)        // 8388608
#define WN_  (C_*C_)        // 1048576
#define NCV_ ((XN_ + 4*WN_)/1024)   // 12288

__global__ __launch_bounds__(256) void prep(const float* __restrict__ x,
                                            const float* __restrict__ w0,
                                            const float* __restrict__ w1,
                                            const float* __restrict__ w2,
                                            const float* __restrict__ w3,
                                            const int*   __restrict__ mask,
                                            __half* __restrict__ xh,
                                            __half* __restrict__ wh)
{
    const int bid = blockIdx.x;
    const int t   = threadIdx.x;
    if (bid == 0 && t < 68) {
        if (t < 4) g_cnt_qkv[t] = 0;
        else       g_cnt_att[t - 4] = 0;
    }
    if (bid < NCV_) {
        long i = ((long)bid * 256 + t) * 4;
        const float* src;
        __half* dst;
        if (i < XN_) { src = x + i; dst = xh + i; }
        else {
            long j = i - XN_;
            int z = (int)(j >> 20);
            const float* w = z == 0 ? w0 : (z == 1 ? w1 : (z == 2 ? w2 : w3));
            src = w + (j & (WN_ - 1));
            dst = wh + j;
        }
        float4 v = *(const float4*)src;
        ((__half2*)dst)[0] = __floats2half2_rn(v.x, v.y);
        ((__half2*)dst)[1] = __floats2half2_rn(v.z, v.w);
    } else {
        __shared__ int s_zero;
        if (t == 0) s_zero = 0;
        __syncthreads();
        const int fid = bid - NCV_;
        const int b  = fid >> 9;
        const int qb = (fid >> 5) & 15;
        const int kb = fid & 31;
        const int* base = mask + ((size_t)b * T_ + qb * 128) * T_ + kb * 64;
        const int r = t >> 1, hh = t & 1;
        const int4* p = (const int4*)(base + (size_t)r * T_ + hh * 32);
        bool ok = true;
#pragma unroll
        for (int i = 0; i < 8; i++) {
            int4 v = p[i];
            ok = ok && (v.x != 0) && (v.y != 0) && (v.z != 0) && (v.w != 0);
        }
        if (!ok) s_zero = 1;
        __syncthreads();
        if (t == 0) g_mflag[fid] = s_zero ? 0 : 1;
    }
}

// ===========================================================================
// GEMM body: C[m,n] = sum_k A[m,k]*W[n,k], single-pass fp16 mma.
// CTA 128x128, BK=64, 3-stage cp.async, 128 threads, 4 warps (64x64 tiles).
// ===========================================================================
#define TILE16 16384
#define NSTG   3
#define STAGE_B (2*TILE16)
#define G_SMEM (NSTG*STAGE_B)         // 98304

#define QSCALE 0.18033688011f         // 0.125 * log2(e)

template<bool HALF_OUT>
__device__ __forceinline__ void gemm_body(const __half* __restrict__ Ag,
                                          const __half* __restrict__ Bz,
                                          void* __restrict__ Cout,
                                          int bx, int by, float oscale)
{
    extern __shared__ char smem_raw[];
    const uint32_t sb = smem_u32a(smem_raw);
    const int K = C_, N = C_;

    const int tid  = threadIdx.x;
    const int w    = tid >> 5;
    const int lane = tid & 31;
    const int wm   = w >> 1;
    const int wn   = w & 1;
    const int m0   = by * 128;
    const int n0   = bx * 128;

    auto prefetch = [&](int t, int s){
        uint32_t st = sb + s * STAGE_B;
        int k0 = t * 64;
#pragma unroll
        for (int i = 0; i < 8; i++) {
            int id = i * 128 + tid;
            int r = id >> 3, c = id & 7;
            uint32_t dsw = (uint32_t)(r * 128 + ((c ^ (r & 7)) << 4));
            CP16(st + dsw,          Ag + (size_t)(m0 + r) * K + k0 + c * 8);
            CP16(st + TILE16 + dsw, Bz + (size_t)(n0 + r) * K + k0 + c * 8);
        }
    };

    prefetch(0, 0); CP_COMMIT();
    prefetch(1, 1); CP_COMMIT();

    float acc[4][8][4];
#pragma unroll
    for (int mi = 0; mi < 4; mi++)
#pragma unroll
        for (int nb = 0; nb < 8; nb++)
#pragma unroll
            for (int j = 0; j < 4; j++) acc[mi][nb][j] = 0.f;

    uint32_t bhf[8][4];
    uint32_t ahf[2][4][4];

    const int NT = K / 64;
    for (int t = 0; t < NT; t++) {
        CP_WAIT1();
        __syncthreads();
        if (t + 2 < NT) prefetch(t + 2, (t + 2) % NSTG);
        CP_COMMIT();

        const uint32_t aB = sb + (t % NSTG) * STAGE_B;
        const uint32_t bB = aB + TILE16;

        auto ldsmB = [&](int kp){
#pragma unroll
            for (int nb = 0; nb < 8; nb++) {
                int r = wn * 64 + nb * 8 + (lane & 7);
                int c = kp * 4 + (lane >> 3);
                ldsm4(bhf[nb], bB + (uint32_t)(r * 128 + ((c ^ (r & 7)) << 4)));
            }
        };
        auto ldsmA = [&](int kk, uint32_t (*dst)[4]){
#pragma unroll
            for (int mi = 0; mi < 4; mi++) {
                int r = wm * 64 + mi * 16 + (lane & 15);
                int c = kk * 2 + (lane >> 4);
                ldsm4(dst[mi], aB + (uint32_t)(r * 128 + ((c ^ (r & 7)) << 4)));
            }
        };
        auto mma_kk = [&](uint32_t (*af)[4], int k2){
#pragma unroll
            for (int mi = 0; mi < 4; mi++)
#pragma unroll
                for (int nb = 0; nb < 8; nb++)
                    mma16816(acc[mi][nb], af[mi], bhf[nb] + k2 * 2);
        };

        ldsmB(0);
        ldsmA(0, ahf[0]);
        ldsmA(1, ahf[1]);
        mma_kk(ahf[0], 0);
        ldsmA(2, ahf[0]);
        mma_kk(ahf[1], 1);
        ldsmB(1);
        ldsmA(3, ahf[1]);
        mma_kk(ahf[0], 0);
        mma_kk(ahf[1], 1);
    }

#pragma unroll
    for (int mi = 0; mi < 4; mi++) {
        int r0 = m0 + wm * 64 + mi * 16 + (lane >> 2);
#pragma unroll
        for (int nb = 0; nb < 8; nb++) {
            int col = n0 + wn * 64 + nb * 8 + (lane & 3) * 2;
            if (HALF_OUT) {
                __half* Ch = (__half*)Cout;
                *(__half2*)(Ch + (size_t)r0 * N + col) =
                    __floats2half2_rn(acc[mi][nb][0] * oscale, acc[mi][nb][1] * oscale);
                *(__half2*)(Ch + (size_t)(r0 + 8) * N + col) =
                    __floats2half2_rn(acc[mi][nb][2] * oscale, acc[mi][nb][3] * oscale);
            } else {
                float* Cf = (float*)Cout;
                *(float2*)(Cf + (size_t)r0 * N + col) =
                    make_float2(acc[mi][nb][0], acc[mi][nb][1]);
                *(float2*)(Cf + (size_t)(r0 + 8) * N + col) =
                    make_float2(acc[mi][nb][2], acc[mi][nb][3]);
            }
        }
    }
}

// ===========================================================================
// Attention body (round-14 best config): 128 q-rows, 4 warps x 2 m-blocks,
// 64-key KV stages (NKV=3), one sync/tile, chunk-pipelined S/PV.
// ===========================================================================
#define AT_ROWB 144
#define OFF_Q   0
#define Q_BYTES (128*AT_ROWB)
#define OFF_KV  Q_BYTES
#define KV_STG  (64*AT_ROWB*2)
#define NKV     3
#define ATT_SMEM (OFF_KV + NKV*KV_STG) // 73728 <= G_SMEM

__device__ __forceinline__ void attn_body(const __half* __restrict__ Q,
                                          const __half* __restrict__ K,
                                          const __half* __restrict__ V,
                                          const int*    __restrict__ mask,
                                          __half* __restrict__ Oh,
                                          int b, int h, int qt)
{
    extern __shared__ char smem_raw[];
    const uint32_t sb = smem_u32a(smem_raw);

    const int tid  = threadIdx.x;
    const int w    = tid >> 5;
    const int lane = tid & 31;
    const int q0   = qt * 128;

    const int pr = tid >> 3;
    const int pc = tid & 7;
    const __half* kg = K + ((size_t)(b * T_) + pr) * C_ + h * D_ + pc * 8;
    const __half* vg = V + ((size_t)(b * T_) + pr) * C_ + h * D_ + pc * 8;
    const uint32_t soff = (uint32_t)(pr * AT_ROWB + pc * 16);
    const uint32_t stg[NKV] = { sb + OFF_KV, sb + OFF_KV + KV_STG, sb + OFF_KV + 2 * KV_STG };

    auto prefetch = [&](const __half* kp, const __half* vp, uint32_t sbase){
#pragma unroll
        for (int i = 0; i < 4; i++) {
            CP16(sbase + soff + i * 16 * AT_ROWB,                 kp + (size_t)i * 16 * C_);
            CP16(sbase + 64 * AT_ROWB + soff + i * 16 * AT_ROWB,  vp + (size_t)i * 16 * C_);
        }
    };

    prefetch(kg, vg, stg[0]); CP_COMMIT();
    prefetch(kg + 64 * C_, vg + 64 * C_, stg[1]); CP_COMMIT();
    const __half* kgn = kg + 128 * C_;
    const __half* vgn = vg + 128 * C_;

#pragma unroll
    for (int i = 0; i < 8; i++) {
        int cid = i * 128 + tid;
        int r = cid >> 3, c = cid & 7;
        *(uint4*)(smem_raw + OFF_Q + r * AT_ROWB + c * 16) =
            *(const uint4*)(Q + (size_t)(b * T_ + q0 + r) * C_ + h * D_ + c * 8);
    }
    __syncthreads();

    uint32_t qf[2][4][4];
#pragma unroll
    for (int m = 0; m < 2; m++)
#pragma unroll
        for (int kd = 0; kd < 4; kd++) {
            uint32_t aq = sb + OFF_Q + (w * 32 + m * 16 + (lane & 15)) * AT_ROWB
                        + (kd * 16 + (lane >> 4) * 8) * 2;
            ldsm4(qf[m][kd], aq);
        }

    float oacc[2][8][4];
#pragma unroll
    for (int m = 0; m < 2; m++)
#pragma unroll
        for (int i = 0; i < 8; i++)
#pragma unroll
            for (int j = 0; j < 4; j++) oacc[m][i][j] = 0.f;
    float lacc[2][4];
#pragma unroll
    for (int m = 0; m < 2; m++)
#pragma unroll
        for (int j = 0; j < 4; j++) lacc[m][j] = 0.f;

    const uint32_t bones[2] = { 0x3C003C00u, 0x3C003C00u };
    const int* mflag_p = g_mflag + (b * 16 + qt) * 32;

    int s_cur = 0, s_pf = 2;
    const int NT = T_ / 64;  // 32
    for (int kt = 0; kt < NT; kt++) {
        CP_WAIT1();
        __syncthreads();
        if (kt + 2 < NT) {
            prefetch(kgn, vgn, stg[s_pf]);
            kgn += 64 * C_; vgn += 64 * C_;
        }
        CP_COMMIT();

        const uint32_t kS = stg[s_cur];
        const uint32_t vS = kS + 64 * AT_ROWB;
        const int flag = mflag_p[kt];
        s_cur = (s_cur == 2) ? 0 : s_cur + 1;
        s_pf  = (s_pf  == 2) ? 0 : s_pf  + 1;

        uint32_t pf[2][4][4];

        auto s_phase = [&](int j, int masked){
            uint32_t kb0[4], kb1[4];
            uint32_t a0 = kS + (j * 8 + (lane & 7)) * AT_ROWB + (lane >> 3) * 16;
            ldsm4(kb0, a0);
            ldsm4(kb1, a0 + 64);
#pragma unroll
            for (int m = 0; m < 2; m++) {
                float sj[4] = {0.f, 0.f, 0.f, 0.f};
                mma16816(sj, qf[m][0], kb0 + 0);
                mma16816(sj, qf[m][1], kb0 + 2);
                mma16816(sj, qf[m][2], kb1 + 0);
                mma16816(sj, qf[m][3], kb1 + 2);

                float e0 = ex2f(sj[0]);
                float e1 = ex2f(sj[1]);
                float e2 = ex2f(sj[2]);
                float e3 = ex2f(sj[3]);
                if (masked) {
                    const int* mp = mask
                        + ((size_t)b * T_ + q0 + w * 32 + m * 16 + (lane >> 2)) * T_
                        + kt * 64 + j * 8 + 2 * (lane & 3);
                    int2 m0v = *(const int2*)mp;
                    int2 m1v = *(const int2*)(mp + 8 * T_);
                    if (m0v.x == 0) e0 = 0.f;
                    if (m0v.y == 0) e1 = 0.f;
                    if (m1v.x == 0) e2 = 0.f;
                    if (m1v.y == 0) e3 = 0.f;
                }
                pf[m][j >> 1][(j & 1) * 2 + 0] = packe(e0, e1);
                pf[m][j >> 1][(j & 1) * 2 + 1] = packe(e2, e3);
            }
        };

        auto pv_phase = [&](int kk){
#pragma unroll
            for (int np = 0; np < 4; np++) {
                uint32_t vb[4];
                uint32_t ad = vS + (kk * 16 + ((lane >> 3) & 1) * 8 + (lane & 7)) * AT_ROWB
                            + (np * 16 + (lane >> 4) * 8) * 2;
                ldsm4t(vb, ad);
#pragma unroll
                for (int m = 0; m < 2; m++) {
                    mma16816(oacc[m][np * 2 + 0], pf[m][kk], vb + 0);
                    mma16816(oacc[m][np * 2 + 1], pf[m][kk], vb + 2);
                }
            }
#pragma unroll
            for (int m = 0; m < 2; m++)
                mma16816(lacc[m], pf[m][kk], bones);
        };

        if (flag) {
            s_phase(0, 0); s_phase(1, 0);
#pragma unroll
            for (int kk = 0; kk < 4; kk++) {
                if (kk < 3) { s_phase(2 * kk + 2, 0); s_phase(2 * kk + 3, 0); }
                pv_phase(kk);
            }
        } else {
            s_phase(0, 1); s_phase(1, 1);
#pragma unroll
            for (int kk = 0; kk < 4; kk++) {
                if (kk < 3) { s_phase(2 * kk + 2, 1); s_phase(2 * kk + 3, 1); }
                pv_phase(kk);
            }
        }
    }

#pragma unroll
    for (int m = 0; m < 2; m++) {
        const float inv0 = 1.f / lacc[m][0];
        const float inv1 = 1.f / lacc[m][2];

        size_t o0 = (size_t)(b * T_ + q0 + w * 32 + m * 16 + (lane >> 2)) * C_
                  + h * D_ + 2 * (lane & 3);
        size_t o1 = o0 + 8 * C_;
#pragma unroll
        for (int nd = 0; nd < 8; nd++) {
            *(__half2*)(Oh + o0 + nd * 8) =
                __floats2half2_rn(oacc[m][nd][0] * inv0, oacc[m][nd][1] * inv0);
            *(__half2*)(Oh + o1 + nd * 8) =
                __floats2half2_rn(oacc[m][nd][2] * inv1, oacc[m][nd][3] * inv1);
        }
    }
}

// ===========================================================================
// Mega-kernel: QKV GEMM (1536 CTAs) -> attention (1024) -> out-proj (512),
// chained by blockIdx-ordered spin counters. 128 threads, 96KB smem, 2 CTA/SM.
// ===========================================================================
#define NG_  1536
#define NA_  1024
#define NO_  512

__global__ __launch_bounds__(128, 2) void mega(const __half* __restrict__ xh,
                                               const __half* __restrict__ wh,
                                               const int*    __restrict__ mask,
                                               __half* __restrict__ Qh,
                                               __half* __restrict__ Kh,
                                               __half* __restrict__ Vh,
                                               __half* __restrict__ Oh,
                                               float*  __restrict__ out)
{
    const int bid = blockIdx.x;
    if (bid < NG_) {
        // y-major order: batch b complete when g_cnt_qkv[b] == 384
        const int y = bid / 24;
        const int r2 = bid % 24;
        const int z = r2 >> 3;
        const int x = r2 & 7;
        __half* Cz = z == 0 ? Qh : (z == 1 ? Kh : Vh);
        gemm_body<true>(xh, wh + (size_t)z * WN_, Cz, x, y, z == 0 ? QSCALE : 1.0f);
        bump_counter(&g_cnt_qkv[y >> 4]);
    } else if (bid < NG_ + NA_) {
        const int k = bid - NG_;
        const int b = k >> 8;
        const int h = (k >> 4) & 15;
        const int qt = k & 15;
        wait_counter(&g_cnt_qkv[b], 384);
        attn_body(Qh, Kh, Vh, mask, Oh, b, h, qt);
        bump_counter(&g_cnt_att[b * 16 + qt]);
    } else {
        const int p = bid - NG_ - NA_;
        const int xo = p & 7;
        const int yo = p >> 3;
        wait_counter(&g_cnt_att[yo], 16);
        gemm_body<false>(Oh, wh + 3 * (size_t)WN_, out, xo, yo, 1.0f);
    }
}

// ===========================================================================
extern "C" void kernel_launch(void* const* d_in, const int* in_sizes, int n_in,
                              void* d_out, int out_size)
{
    const float* x    = (const float*)d_in[0];
    const int*   mask = (const int*)  d_in[1];
    const float* Wq   = (const float*)d_in[2];
    const float* Wk   = (const float*)d_in[3];
    const float* Wv   = (const float*)d_in[4];
    const float* Wo   = (const float*)d_in[5];
    float* out = (float*)d_out;

    __half *Qh, *Kh, *Vh, *xh, *wh, *Oh;
    cudaGetSymbolAddress((void**)&Qh, g_Qh);
    cudaGetSymbolAddress((void**)&Kh, g_Kh);
    cudaGetSymbolAddress((void**)&Vh, g_Vh);
    cudaGetSymbolAddress((void**)&xh, g_xh);
    cudaGetSymbolAddress((void**)&wh, g_wh);
    cudaGetSymbolAddress((void**)&Oh, g_Oh);

    cudaFuncSetAttribute(mega, cudaFuncAttributeMaxDynamicSharedMemorySize, G_SMEM);

    prep<<<NCV_ + B_ * 16 * 32, 256>>>(x, Wq, Wk, Wv, Wo, mask, xh, wh);
    mega<<<NG_ + NA_ + NO_, 128, G_SMEM>>>(xh, wh, mask, Qh, Kh, Vh, Oh, out);
}